// round 15
// baseline (speedup 1.0000x reference)
#include <cuda_runtime.h>
#include <cuda_bf16.h>
#include <math.h>
#include <stdint.h>

#define D      1024
#define CLS    16
#define NSAMP  4096
#define MQ     4096
#define NT     16

__device__ float g_Sigma[CLS][D][D];
__device__ float g_V[CLS][D][D];
__device__ float g_T1[CLS][262144];
__device__ float g_Base[D][D];
__device__ float g_L[D][D];
__device__ float g_part[8][CLS][D];
__device__ float g_mu[CLS][D];
__device__ float g_s[CLS][D];
__device__ float g_nx[MQ];
__device__ float g_xm[MQ][CLS];
__device__ float g_ssc[CLS];
__device__ float g_mmc[CLS];
__device__ int   g_cnt[CLS];
__device__ int   g_cntp[8][CLS];
__device__ int   g_start[CLS];
__device__ int   g_idx[NSAMP];
__device__ float g_kap;
__device__ float g_coef[CLS];
__device__ float g_invscale[CLS];

__device__ __nv_bfloat16 g_Xqh[MQ][D];
__device__ __nv_bfloat16 g_Xql[MQ][D];
__device__ __nv_bfloat16 g_Vh[CLS][D][D];
__device__ __nv_bfloat16 g_Vl[CLS][D][D];

__device__ __forceinline__ uint32_t smem_u32(const void* p) {
    uint32_t a;
    asm("{ .reg .u64 t; cvta.to.shared.u64 t, %1; cvt.u32.u64 %0, t; }" : "=r"(a) : "l"(p));
    return a;
}
__device__ __forceinline__ void ldsm4(uint32_t* r, uint32_t a) {
    asm volatile("ldmatrix.sync.aligned.m8n8.x4.shared.b16 {%0,%1,%2,%3}, [%4];"
                 : "=r"(r[0]), "=r"(r[1]), "=r"(r[2]), "=r"(r[3]) : "r"(a));
}
__device__ __forceinline__ void mma16816(float* d, const uint32_t* a, const uint32_t* b) {
    asm volatile(
        "mma.sync.aligned.m16n8k16.row.col.f32.bf16.bf16.f32 "
        "{%0,%1,%2,%3}, {%4,%5,%6,%7}, {%8,%9}, {%0,%1,%2,%3};"
        : "+f"(d[0]), "+f"(d[1]), "+f"(d[2]), "+f"(d[3])
        : "r"(a[0]), "r"(a[1]), "r"(a[2]), "r"(a[3]), "r"(b[0]), "r"(b[1]));
}
__device__ __forceinline__ void mma_tf32(float* d, const uint32_t* a, const uint32_t* b) {
    asm volatile(
        "mma.sync.aligned.m16n8k8.row.col.f32.tf32.tf32.f32 "
        "{%0,%1,%2,%3}, {%4,%5,%6,%7}, {%8,%9}, {%0,%1,%2,%3};"
        : "+f"(d[0]), "+f"(d[1]), "+f"(d[2]), "+f"(d[3])
        : "r"(a[0]), "r"(a[1]), "r"(a[2]), "r"(a[3]), "r"(b[0]), "r"(b[1]));
}
__device__ __forceinline__ float tf32_rn(float x) {
    uint32_t u;
    asm("cvt.rna.tf32.f32 %0, %1;" : "=r"(u) : "f"(x));
    return __uint_as_float(u);
}
__device__ __forceinline__ void cpa16(uint32_t s, const void* g) {
    asm volatile("{ .reg .u64 gg; cvta.to.global.u64 gg, %1; cp.async.ca.shared.global [%0], [gg], 16; }"
                 :: "r"(s), "l"(g) : "memory");
}
#define CPA_COMMIT asm volatile("cp.async.commit_group;" ::: "memory")
#define CPA_WAIT1  asm volatile("cp.async.wait_group 1;" ::: "memory")
#define CPA_WAIT0  asm volatile("cp.async.wait_group 0;" ::: "memory")
#define FB(x) (__float_as_uint(x))
#define MMA3(d, ah, bh, al, bl) { mma_tf32(d, ah, bh); mma_tf32(d, ah, bl); mma_tf32(d, al, bh); }

__device__ __forceinline__ void writeV(int c, int i, int j, float v) {
    g_V[c][i][j] = v;
    __nv_bfloat16 hb = __float2bfloat16(v);
    g_Vh[c][i][j] = hb;
    g_Vl[c][i][j] = __float2bfloat16(v - __bfloat162float(hb));
}

// race-free row-owner Cholesky factor (lower) + column-wise inverse -> writeV
__device__ __forceinline__ void chol_factor_invert(float (*Ds)[65], int tid, int c, int base) {
    for (int j = 0; j < 64; j++) {
        float s = sqrtf(Ds[j][j]);
        if (tid > j && tid < 64) Ds[tid][j] /= s;
        __syncthreads();
        if (tid == j) Ds[j][j] = s;
        if (tid > j && tid < 64) {
            float lij = Ds[tid][j];
            for (int kc = j + 1; kc <= tid; kc++) Ds[tid][kc] -= lij * Ds[kc][j];
        }
        __syncthreads();
    }
    if (tid < 64) {
        int j = tid;
        float x[64];
#pragma unroll
        for (int i = 0; i < 64; i++) {
            float tv = (i == j) ? 1.0f : 0.0f;
#pragma unroll
            for (int k = 0; k < i; k++) tv -= Ds[i][k] * x[k];
            x[i] = tv / Ds[i][i];
        }
#pragma unroll
        for (int i = 0; i < 64; i++) writeV(c, base + i, base + j, x[i]);
    }
}

// ---------------- stats ----------------
__global__ void k_stats1(const float* __restrict__ X, const int* __restrict__ y) {
    __shared__ int sy[512];
    int tid = threadIdx.x;
    int r0 = blockIdx.y * 512;
    for (int n = tid; n < 512; n += 128) sy[n] = y[r0 + n];
    __syncthreads();
    int k = blockIdx.x * 128 + tid;
    float acc[CLS];
#pragma unroll
    for (int c = 0; c < CLS; c++) acc[c] = 0.f;
    for (int n = 0; n < 512; n++) {
        float v = X[(size_t)(r0 + n) * D + k];
        int cls = sy[n];
#pragma unroll
        for (int c = 0; c < CLS; c++) acc[c] += (cls == c) ? v : 0.f;
    }
#pragma unroll
    for (int c = 0; c < CLS; c++) g_part[blockIdx.y][c][k] = acc[c];
    if (blockIdx.x == 0) {
        __shared__ int scnt[CLS];
        if (tid < CLS) scnt[tid] = 0;
        __syncthreads();
        for (int n = tid; n < 512; n += 128) atomicAdd(&scnt[sy[n]], 1);
        __syncthreads();
        if (tid < CLS) g_cntp[blockIdx.y][tid] = scnt[tid];
    }
}
__global__ void k_sort_params(const int* __restrict__ y, const float* __restrict__ kappa,
                              const float* __restrict__ nu) {
    __shared__ int s_start[CLS];
    int lane = threadIdx.x;
    if (lane == 0) {
        int s = 0;
        for (int c = 0; c < CLS; c++) {
            int t = 0;
            for (int r = 0; r < 8; r++) t += g_cntp[r][c];
            g_cnt[c] = t; g_start[c] = s; s_start[c] = s; s += t;
        }
        float kap = fabsf(kappa[0]) + 1e-6f;
        g_kap = kap;
        float nu_ = fmaxf(nu[0], (float)(D - 1) + 1e-6f);
        for (int c = 0; c < CLS; c++) {
            float Nj = (float)g_cnt[c];
            g_coef[c] = kap + Nj;
            g_invscale[c] = 1.0f / (nu_ + Nj + (float)D + 2.0f);
        }
    }
    __syncthreads();
    int off[CLS];
#pragma unroll
    for (int c = 0; c < CLS; c++) off[c] = s_start[c];
    unsigned below = (1u << lane) - 1u;
    for (int n0 = 0; n0 < NSAMP; n0 += 32) {
        int v = y[n0 + lane];
#pragma unroll
        for (int c = 0; c < CLS; c++) {
            unsigned m = __ballot_sync(0xffffffffu, v == c);
            if (v == c) g_idx[off[c] + __popc(m & below)] = n0 + lane;
            off[c] += __popc(m);
        }
    }
}
__global__ void k_mu(const float* __restrict__ m) {
    int c = blockIdx.y;
    int k = blockIdx.x * blockDim.x + threadIdx.x;
    float s = 0.f;
#pragma unroll
    for (int r = 0; r < 8; r++) s += g_part[r][c][k];
    g_mu[c][k] = (g_kap * m[k] + s) / g_coef[c];
}
__global__ void k_buildL(const float* __restrict__ td, const float* __restrict__ tl) {
    int i = blockIdx.x;
    for (int k = threadIdx.x; k < D; k += blockDim.x) {
        float v;
        if (k < i) v = tl[(size_t)i * D + k];
        else if (k == i) v = fabsf(td[i]);
        else v = 0.f;
        g_L[i][k] = v;
    }
}

// ---------------- Base = L L^T + kap m m^T (triangular skip) ----------------
__global__ __launch_bounds__(256) void k_base(const float* __restrict__ m) {
    __shared__ float As[16][65];
    __shared__ float Bs[16][65];
    int i0 = blockIdx.x * 64, j0 = blockIdx.y * 64;
    int tid = threadIdx.x, tx = tid & 15, ty = tid >> 4;
    float acc[4][4] = {};
    int kend = ((i0 < j0) ? i0 : j0) + 64;
    for (int k0 = 0; k0 < kend; k0 += 16) {
#pragma unroll
        for (int t = 0; t < 4; t++) {
            int idx = tid + 256 * t;
            int ii = idx >> 4, kk = idx & 15;
            As[kk][ii] = g_L[i0 + ii][k0 + kk];
            Bs[kk][ii] = g_L[j0 + ii][k0 + kk];
        }
        __syncthreads();
#pragma unroll
        for (int kk = 0; kk < 16; kk++) {
            float a[4], b[4];
#pragma unroll
            for (int q = 0; q < 4; q++) a[q] = As[kk][4 * ty + q];
#pragma unroll
            for (int q = 0; q < 4; q++) b[q] = Bs[kk][4 * tx + q];
#pragma unroll
            for (int p = 0; p < 4; p++)
#pragma unroll
                for (int q = 0; q < 4; q++) acc[p][q] += a[p] * b[q];
        }
        __syncthreads();
    }
    float kap = g_kap;
#pragma unroll
    for (int p = 0; p < 4; p++) {
        int i = i0 + 4 * ty + p;
        float mi = m[i];
#pragma unroll
        for (int q = 0; q < 4; q++) {
            int j = j0 + 4 * tx + q;
            g_Base[i][j] = acc[p][q] + kap * mi * m[j];
        }
    }
}

// ---------------- Sigma = (Base + S - coef*mu mu^T)*invscale (tf32-split mma) -----
__global__ __launch_bounds__(256) void k_sigma_mma(const float* __restrict__ X) {
    __shared__ float Ah[16][136], Al[16][136];
    __shared__ float Bh[16][72],  Bl[16][72];
    int c = blockIdx.z;
    int i0 = blockIdx.x * 128, j0 = blockIdx.y * 64;
    int tid = threadIdx.x, lane = tid & 31, wid = tid >> 5;
    int wm = wid >> 1, wn = wid & 1;
    int r = lane >> 2, q = lane & 3;
    int cnt = g_cnt[c], start = g_start[c];
    float acc[2][4][4] = {};
    int kmax = (cnt + 15) & ~15;
    for (int k0 = 0; k0 < kmax; k0 += 16) {
        __syncthreads();
#pragma unroll
        for (int t = 0; t < 8; t++) {
            int e = tid + 256 * t;
            int kk = e >> 7, col = e & 127;
            int krow = k0 + kk;
            float v = (krow < cnt) ? X[(size_t)g_idx[start + krow] * D + i0 + col] : 0.f;
            float h = tf32_rn(v);
            Ah[kk][col] = h; Al[kk][col] = tf32_rn(v - h);
        }
#pragma unroll
        for (int t = 0; t < 4; t++) {
            int e = tid + 256 * t;
            int kk = e >> 6, col = e & 63;
            int krow = k0 + kk;
            float v = (krow < cnt) ? X[(size_t)g_idx[start + krow] * D + j0 + col] : 0.f;
            float h = tf32_rn(v);
            Bh[kk][col] = h; Bl[kk][col] = tf32_rn(v - h);
        }
        __syncthreads();
#pragma unroll
        for (int ks = 0; ks < 2; ks++) {
            int k8 = ks * 8;
            uint32_t ah[2][4], al[2][4], bh[4][2], bl[4][2];
#pragma unroll
            for (int ms = 0; ms < 2; ms++) {
                int mb = wm * 32 + ms * 16;
                ah[ms][0] = FB(Ah[k8 + q][mb + r]);     ah[ms][1] = FB(Ah[k8 + q][mb + 8 + r]);
                ah[ms][2] = FB(Ah[k8 + 4 + q][mb + r]); ah[ms][3] = FB(Ah[k8 + 4 + q][mb + 8 + r]);
                al[ms][0] = FB(Al[k8 + q][mb + r]);     al[ms][1] = FB(Al[k8 + q][mb + 8 + r]);
                al[ms][2] = FB(Al[k8 + 4 + q][mb + r]); al[ms][3] = FB(Al[k8 + 4 + q][mb + 8 + r]);
            }
#pragma unroll
            for (int nt = 0; nt < 4; nt++) {
                int nb = wn * 32 + nt * 8;
                bh[nt][0] = FB(Bh[k8 + q][nb + r]); bh[nt][1] = FB(Bh[k8 + 4 + q][nb + r]);
                bl[nt][0] = FB(Bl[k8 + q][nb + r]); bl[nt][1] = FB(Bl[k8 + 4 + q][nb + r]);
            }
#pragma unroll
            for (int ms = 0; ms < 2; ms++)
#pragma unroll
                for (int nt = 0; nt < 4; nt++)
                    MMA3(acc[ms][nt], ah[ms], bh[nt], al[ms], bl[nt]);
        }
    }
    float coef = g_coef[c], inv = g_invscale[c];
#pragma unroll
    for (int ms = 0; ms < 2; ms++)
#pragma unroll
        for (int nt = 0; nt < 4; nt++) {
            int i = i0 + wm * 32 + ms * 16 + r;
            int j = j0 + wn * 32 + nt * 8 + 2 * q;
            float* d = acc[ms][nt];
            float mui = g_mu[c][i], mui8 = g_mu[c][i + 8];
            float mj0 = g_mu[c][j], mj1 = g_mu[c][j + 1];
            g_Sigma[c][i][j]         = (g_Base[i][j]         + d[0] - coef * mui  * mj0) * inv;
            g_Sigma[c][i][j + 1]     = (g_Base[i][j + 1]     + d[1] - coef * mui  * mj1) * inv;
            g_Sigma[c][i + 8][j]     = (g_Base[i + 8][j]     + d[2] - coef * mui8 * mj0) * inv;
            g_Sigma[c][i + 8][j + 1] = (g_Base[i + 8][j + 1] + d[3] - coef * mui8 * mj1) * inv;
        }
}

// ---------------- initial diag ----------------
__global__ __launch_bounds__(256) void k_chol_diag0() {
    __shared__ float Ds[64][65];
    int c = blockIdx.x;
    int tid = threadIdx.x;
    for (int e = tid; e < 4096; e += 256)
        Ds[e >> 6][e & 63] = g_Sigma[c][e >> 6][e & 63];
    __syncthreads();
    chol_factor_invert(Ds, tid, c, 0);
}

// ---------------- panel P = A21 * invL11^T (tf32) ----------------
__global__ __launch_bounds__(128) void k_pgemm(int kb) {
    __shared__ float Ah[64][20], Al[64][20], Bh[64][20], Bl[64][20];
    int c = blockIdx.y;
    int kbase = kb * 64;
    int i0 = kbase + 64 + blockIdx.x * 64;
    int tid = threadIdx.x, lane = tid & 31, wid = tid >> 5;
    int wy = wid >> 1, wx = wid & 1;
    int r = lane >> 2, q = lane & 3;
    float acc[2][4][4] = {};
    for (int k0 = 0; k0 < 64; k0 += 16) {
        __syncthreads();
#pragma unroll
        for (int t = 0; t < 8; t++) {
            int e = tid + 128 * t;
            int i = e >> 4, k = e & 15;
            float va = g_Sigma[c][i0 + i][kbase + k0 + k];
            float h = tf32_rn(va);
            Ah[i][k] = h; Al[i][k] = tf32_rn(va - h);
            float vb = g_V[c][kbase + i][kbase + k0 + k];
            h = tf32_rn(vb);
            Bh[i][k] = h; Bl[i][k] = tf32_rn(vb - h);
        }
        __syncthreads();
#pragma unroll
        for (int ks = 0; ks < 2; ks++) {
            int k8 = ks * 8;
            uint32_t ah[2][4], al[2][4], bh[4][2], bl[4][2];
#pragma unroll
            for (int ms = 0; ms < 2; ms++) {
                int mb = wy * 32 + ms * 16;
                ah[ms][0] = FB(Ah[mb + r][k8 + q]);     ah[ms][1] = FB(Ah[mb + 8 + r][k8 + q]);
                ah[ms][2] = FB(Ah[mb + r][k8 + 4 + q]); ah[ms][3] = FB(Ah[mb + 8 + r][k8 + 4 + q]);
                al[ms][0] = FB(Al[mb + r][k8 + q]);     al[ms][1] = FB(Al[mb + 8 + r][k8 + q]);
                al[ms][2] = FB(Al[mb + r][k8 + 4 + q]); al[ms][3] = FB(Al[mb + 8 + r][k8 + 4 + q]);
            }
#pragma unroll
            for (int nt = 0; nt < 4; nt++) {
                int nb = wx * 32 + nt * 8;
                bh[nt][0] = FB(Bh[nb + r][k8 + q]); bh[nt][1] = FB(Bh[nb + r][k8 + 4 + q]);
                bl[nt][0] = FB(Bl[nb + r][k8 + q]); bl[nt][1] = FB(Bl[nb + r][k8 + 4 + q]);
            }
#pragma unroll
            for (int ms = 0; ms < 2; ms++)
#pragma unroll
                for (int nt = 0; nt < 4; nt++)
                    MMA3(acc[ms][nt], ah[ms], bh[nt], al[ms], bl[nt]);
        }
    }
    __syncthreads();
#pragma unroll
    for (int ms = 0; ms < 2; ms++)
#pragma unroll
        for (int nt = 0; nt < 4; nt++) {
            int i = i0 + wy * 32 + ms * 16 + r;
            int j = kbase + wx * 32 + nt * 8 + 2 * q;
            float* d = acc[ms][nt];
            g_Sigma[c][i][j]         = d[0];
            g_Sigma[c][i][j + 1]     = d[1];
            g_Sigma[c][i + 8][j]     = d[2];
            g_Sigma[c][i + 8][j + 1] = d[3];
        }
}

// ---------------- trailing syrk (tf32) + fused next-diag (race-free fast) ---------
__global__ __launch_bounds__(128) void k_trail_mma(int kb) {
    __shared__ char buf[20480];
    float (*Ah)[20] = (float(*)[20])buf;
    float (*Al)[20] = (float(*)[20])(buf + 5120);
    float (*Bh)[20] = (float(*)[20])(buf + 10240);
    float (*Bl)[20] = (float(*)[20])(buf + 15360);
    int c = blockIdx.y;
    int pidx = blockIdx.x;
    int ti = kb + 1;
    while (pidx >= ti - kb) { pidx -= ti - kb; ti++; }
    int tj = kb + 1 + pidx;
    int i0 = ti * 64, j0 = tj * 64, kbase = kb * 64;
    int tid = threadIdx.x, lane = tid & 31, wid = tid >> 5;
    int wy = wid >> 1, wx = wid & 1;
    int r = lane >> 2, q = lane & 3;
    float acc[2][4][4] = {};
    for (int k0 = 0; k0 < 64; k0 += 16) {
        __syncthreads();
#pragma unroll
        for (int t = 0; t < 8; t++) {
            int e = tid + 128 * t;
            int i = e >> 4, k = e & 15;
            float va = g_Sigma[c][i0 + i][kbase + k0 + k];
            float h = tf32_rn(va);
            Ah[i][k] = h; Al[i][k] = tf32_rn(va - h);
            float vb = g_Sigma[c][j0 + i][kbase + k0 + k];
            h = tf32_rn(vb);
            Bh[i][k] = h; Bl[i][k] = tf32_rn(vb - h);
        }
        __syncthreads();
#pragma unroll
        for (int ks = 0; ks < 2; ks++) {
            int k8 = ks * 8;
            uint32_t ah[2][4], al[2][4], bh[4][2], bl[4][2];
#pragma unroll
            for (int ms = 0; ms < 2; ms++) {
                int mb = wy * 32 + ms * 16;
                ah[ms][0] = FB(Ah[mb + r][k8 + q]);     ah[ms][1] = FB(Ah[mb + 8 + r][k8 + q]);
                ah[ms][2] = FB(Ah[mb + r][k8 + 4 + q]); ah[ms][3] = FB(Ah[mb + 8 + r][k8 + 4 + q]);
                al[ms][0] = FB(Al[mb + r][k8 + q]);     al[ms][1] = FB(Al[mb + 8 + r][k8 + q]);
                al[ms][2] = FB(Al[mb + r][k8 + 4 + q]); al[ms][3] = FB(Al[mb + 8 + r][k8 + 4 + q]);
            }
#pragma unroll
            for (int nt = 0; nt < 4; nt++) {
                int nb = wx * 32 + nt * 8;
                bh[nt][0] = FB(Bh[nb + r][k8 + q]); bh[nt][1] = FB(Bh[nb + r][k8 + 4 + q]);
                bl[nt][0] = FB(Bl[nb + r][k8 + q]); bl[nt][1] = FB(Bl[nb + r][k8 + 4 + q]);
            }
#pragma unroll
            for (int ms = 0; ms < 2; ms++)
#pragma unroll
                for (int nt = 0; nt < 4; nt++)
                    MMA3(acc[ms][nt], ah[ms], bh[nt], al[ms], bl[nt]);
        }
    }
    __syncthreads();
#pragma unroll
    for (int ms = 0; ms < 2; ms++)
#pragma unroll
        for (int nt = 0; nt < 4; nt++) {
            int i = i0 + wy * 32 + ms * 16 + r;
            int j = j0 + wx * 32 + nt * 8 + 2 * q;
            float* d = acc[ms][nt];
            g_Sigma[c][i][j]         -= d[0];
            g_Sigma[c][i][j + 1]     -= d[1];
            g_Sigma[c][i + 8][j]     -= d[2];
            g_Sigma[c][i + 8][j + 1] -= d[3];
        }
    if (blockIdx.x == 0) {
        int base = (kb + 1) * 64;
        __syncthreads();
        float (*Ds)[65] = (float(*)[65])buf;
        for (int e = tid; e < 4096; e += 128)
            Ds[e >> 6][e & 63] = g_Sigma[c][base + (e >> 6)][base + (e & 63)];
        __syncthreads();
        chol_factor_invert(Ds, tid, c, base);
    }
}

// ---------------- recursive triinv stage GEMM 1: T1 = A21 * V11 -------------------
__global__ __launch_bounds__(128) void k_tri1(int h) {
    __shared__ float Ah[64][20], Al[64][20], Bh[16][72], Bl[16][72];
    int c = blockIdx.y;
    int tpr = h >> 6, t2 = tpr * tpr;
    int p = blockIdx.x / t2;
    int rem = blockIdx.x % t2;
    int mi = rem / tpr, ni = rem % tpr;
    int base = p * 2 * h;
    int r0 = base + h + mi * 64;
    int n0 = ni * 64;
    int tid = threadIdx.x, lane = tid & 31, wid = tid >> 5;
    int wy = wid >> 1, wx = wid & 1;
    int r = lane >> 2, q = lane & 3;
    float acc[2][4][4] = {};
    for (int k0 = 0; k0 < h; k0 += 16) {
        __syncthreads();
        for (int t = 0; t < 8; t++) {
            int e = tid + 128 * t;
            {
                int i = e >> 4, k = e & 15;
                float v = g_Sigma[c][r0 + i][base + k0 + k];
                float hh = tf32_rn(v);
                Ah[i][k] = hh; Al[i][k] = tf32_rn(v - hh);
            }
            {
                int k = e >> 6, j = e & 63;
                float v = ((k0 + k) >= (n0 + j)) ? g_V[c][base + k0 + k][base + n0 + j] : 0.f;
                float hh = tf32_rn(v);
                Bh[k][j] = hh; Bl[k][j] = tf32_rn(v - hh);
            }
        }
        __syncthreads();
#pragma unroll
        for (int ks = 0; ks < 2; ks++) {
            int k8 = ks * 8;
            uint32_t ah[2][4], al[2][4], bh[4][2], bl[4][2];
#pragma unroll
            for (int ms = 0; ms < 2; ms++) {
                int mb = wy * 32 + ms * 16;
                ah[ms][0] = FB(Ah[mb + r][k8 + q]);     ah[ms][1] = FB(Ah[mb + 8 + r][k8 + q]);
                ah[ms][2] = FB(Ah[mb + r][k8 + 4 + q]); ah[ms][3] = FB(Ah[mb + 8 + r][k8 + 4 + q]);
                al[ms][0] = FB(Al[mb + r][k8 + q]);     al[ms][1] = FB(Al[mb + 8 + r][k8 + q]);
                al[ms][2] = FB(Al[mb + r][k8 + 4 + q]); al[ms][3] = FB(Al[mb + 8 + r][k8 + 4 + q]);
            }
#pragma unroll
            for (int nt = 0; nt < 4; nt++) {
                int nb = wx * 32 + nt * 8;
                bh[nt][0] = FB(Bh[k8 + q][nb + r]); bh[nt][1] = FB(Bh[k8 + 4 + q][nb + r]);
                bl[nt][0] = FB(Bl[k8 + q][nb + r]); bl[nt][1] = FB(Bl[k8 + 4 + q][nb + r]);
            }
#pragma unroll
            for (int ms = 0; ms < 2; ms++)
#pragma unroll
                for (int nt = 0; nt < 4; nt++)
                    MMA3(acc[ms][nt], ah[ms], bh[nt], al[ms], bl[nt]);
        }
    }
    int pb = p * h * h;
#pragma unroll
    for (int ms = 0; ms < 2; ms++)
#pragma unroll
        for (int nt = 0; nt < 4; nt++) {
            int il = mi * 64 + wy * 32 + ms * 16 + r;
            int jl = n0 + wx * 32 + nt * 8 + 2 * q;
            float* d = acc[ms][nt];
            g_T1[c][pb + il * h + jl]           = d[0];
            g_T1[c][pb + il * h + jl + 1]       = d[1];
            g_T1[c][pb + (il + 8) * h + jl]     = d[2];
            g_T1[c][pb + (il + 8) * h + jl + 1] = d[3];
        }
}

// ---------------- stage GEMM 2: V21 = -V22 * T1 (writes V + bf16) -----------------
__global__ __launch_bounds__(128) void k_tri2(int h) {
    __shared__ float Ah[64][20], Al[64][20], Bh[16][72], Bl[16][72];
    int c = blockIdx.y;
    int tpr = h >> 6, t2 = tpr * tpr;
    int p = blockIdx.x / t2;
    int rem = blockIdx.x % t2;
    int mi = rem / tpr, ni = rem % tpr;
    int base = p * 2 * h;
    int rv = base + h;
    int n0 = ni * 64;
    int tid = threadIdx.x, lane = tid & 31, wid = tid >> 5;
    int wy = wid >> 1, wx = wid & 1;
    int r = lane >> 2, q = lane & 3;
    int pb = p * h * h;
    float acc[2][4][4] = {};
    for (int k0 = 0; k0 < h; k0 += 16) {
        __syncthreads();
        for (int t = 0; t < 8; t++) {
            int e = tid + 128 * t;
            {
                int i = e >> 4, k = e & 15;
                float v = ((mi * 64 + i) >= (k0 + k)) ? g_V[c][rv + mi * 64 + i][rv + k0 + k] : 0.f;
                float hh = tf32_rn(v);
                Ah[i][k] = hh; Al[i][k] = tf32_rn(v - hh);
            }
            {
                int k = e >> 6, j = e & 63;
                float v = g_T1[c][pb + (k0 + k) * h + n0 + j];
                float hh = tf32_rn(v);
                Bh[k][j] = hh; Bl[k][j] = tf32_rn(v - hh);
            }
        }
        __syncthreads();
#pragma unroll
        for (int ks = 0; ks < 2; ks++) {
            int k8 = ks * 8;
            uint32_t ah[2][4], al[2][4], bh[4][2], bl[4][2];
#pragma unroll
            for (int ms = 0; ms < 2; ms++) {
                int mb = wy * 32 + ms * 16;
                ah[ms][0] = FB(Ah[mb + r][k8 + q]);     ah[ms][1] = FB(Ah[mb + 8 + r][k8 + q]);
                ah[ms][2] = FB(Ah[mb + r][k8 + 4 + q]); ah[ms][3] = FB(Ah[mb + 8 + r][k8 + 4 + q]);
                al[ms][0] = FB(Al[mb + r][k8 + q]);     al[ms][1] = FB(Al[mb + 8 + r][k8 + q]);
                al[ms][2] = FB(Al[mb + r][k8 + 4 + q]); al[ms][3] = FB(Al[mb + 8 + r][k8 + 4 + q]);
            }
#pragma unroll
            for (int nt = 0; nt < 4; nt++) {
                int nb = wx * 32 + nt * 8;
                bh[nt][0] = FB(Bh[k8 + q][nb + r]); bh[nt][1] = FB(Bh[k8 + 4 + q][nb + r]);
                bl[nt][0] = FB(Bl[k8 + q][nb + r]); bl[nt][1] = FB(Bl[k8 + 4 + q][nb + r]);
            }
#pragma unroll
            for (int ms = 0; ms < 2; ms++)
#pragma unroll
                for (int nt = 0; nt < 4; nt++)
                    MMA3(acc[ms][nt], ah[ms], bh[nt], al[ms], bl[nt]);
        }
    }
#pragma unroll
    for (int ms = 0; ms < 2; ms++)
#pragma unroll
        for (int nt = 0; nt < 4; nt++) {
            int ig = rv + mi * 64 + wy * 32 + ms * 16 + r;
            int jg = base + n0 + wx * 32 + nt * 8 + 2 * q;
            float* d = acc[ms][nt];
            writeV(c, ig, jg, -d[0]);
            writeV(c, ig, jg + 1, -d[1]);
            writeV(c, ig + 8, jg, -d[2]);
            writeV(c, ig + 8, jg + 1, -d[3]);
        }
}

// ---------------- conversions / small vec kernels ----------------
__global__ void k_cvt_xq(const float* __restrict__ Xq) {
    int i = blockIdx.x * 256 + threadIdx.x;
    float x = Xq[i];
    __nv_bfloat16 h = __float2bfloat16(x);
    ((__nv_bfloat16*)g_Xqh)[i] = h;
    ((__nv_bfloat16*)g_Xql)[i] = __float2bfloat16(x - __bfloat162float(h));
}
__global__ void k_svec() {
    int c = blockIdx.y;
    int warp = threadIdx.x >> 5, lane = threadIdx.x & 31;
    int row = blockIdx.x * 8 + warp;
    float acc = 0.f;
    for (int k = lane; k <= row; k += 32) acc += g_V[c][row][k] * g_mu[c][k];
    for (int o = 16; o > 0; o >>= 1) acc += __shfl_down_sync(0xffffffffu, acc, o);
    if (lane == 0) g_s[c][row] = acc;
}
__global__ void k_scalars() {
    int c = blockIdx.x;
    __shared__ float r1[256], r2[256];
    float a = 0.f, b = 0.f;
    for (int k = threadIdx.x; k < D; k += 256) {
        float sv = g_s[c][k];  a += sv * sv;
        float mv = g_mu[c][k]; b += mv * mv;
    }
    r1[threadIdx.x] = a; r2[threadIdx.x] = b;
    __syncthreads();
    for (int o = 128; o > 0; o >>= 1) {
        if (threadIdx.x < o) { r1[threadIdx.x] += r1[threadIdx.x + o]; r2[threadIdx.x] += r2[threadIdx.x + o]; }
        __syncthreads();
    }
    if (threadIdx.x == 0) { g_ssc[c] = r1[0]; g_mmc[c] = r2[0]; }
}
__global__ void k_nxm(const float* __restrict__ Xq) {
    int warp = threadIdx.x >> 5, lane = threadIdx.x & 31;
    int row = blockIdx.x * 8 + warp;
    float acc[CLS + 1];
#pragma unroll
    for (int c = 0; c <= CLS; c++) acc[c] = 0.f;
    for (int k = lane; k < D; k += 32) {
        float v = Xq[(size_t)row * D + k];
        acc[CLS] += v * v;
#pragma unroll
        for (int c = 0; c < CLS; c++) acc[c] += v * g_mu[c][k];
    }
#pragma unroll
    for (int c = 0; c <= CLS; c++) {
        float a = acc[c];
        for (int o = 16; o > 0; o >>= 1) a += __shfl_down_sync(0xffffffffu, a, o);
        if (lane == 0) {
            if (c < CLS) g_xm[row][c] = a;
            else g_nx[row] = a;
        }
    }
}

// ====== logits: bf16-split mma, 4-jt group + cp.async double-buffered =============
#define LG5_ROWB  144
#define LG5_SAH   0
#define LG5_SAL   18432
#define LG5_SBH   36864
#define LG5_SBL   73728
#define LG5_STAGE 110592
#define LG5_SMEM  221184

__device__ __forceinline__ void lg_stage(uint32_t sb, int s, int c, int m0, int jt0,
                                         int kt, int tid) {
    uint32_t base = sb + (uint32_t)(s * LG5_STAGE);
#pragma unroll
    for (int t = 0; t < 4; t++) {
        int idx = tid + 256 * t;
        int r = idx >> 3, c8 = idx & 7;
        uint32_t off = (uint32_t)(r * LG5_ROWB + c8 * 16);
        cpa16(base + LG5_SAH + off, &g_Xqh[m0 + r][kt * 64 + c8 * 8]);
        cpa16(base + LG5_SAL + off, &g_Xql[m0 + r][kt * 64 + c8 * 8]);
    }
#pragma unroll
    for (int t = 0; t < 8; t++) {
        int idx = tid + 256 * t;
        int tt = idx >> 9;
        int rr = (idx >> 3) & 63, c8 = idx & 7;
        uint32_t off = (uint32_t)(tt * 9216 + rr * LG5_ROWB + c8 * 16);
        int row = (jt0 + tt) * 64 + rr;
        cpa16(base + LG5_SBH + off, &g_Vh[c][row][kt * 64 + c8 * 8]);
        cpa16(base + LG5_SBL + off, &g_Vl[c][row][kt * 64 + c8 * 8]);
    }
}

__global__ __launch_bounds__(256) void k_logits_mma(float* __restrict__ out) {
    extern __shared__ char smem[];
    uint32_t sb = smem_u32(smem);
    int tid = threadIdx.x, lane = tid & 31, wid = tid >> 5;
    int wm = wid >> 1, wn = wid & 1;
    int c = blockIdx.y, m0 = blockIdx.x * 128;

    uint32_t aoff = (uint32_t)((wm * 32 + (lane & 15)) * LG5_ROWB + (lane >> 4) * 16);
    uint32_t boff = (uint32_t)((wn * 32 + ((lane & 16) >> 1) + (lane & 7)) * LG5_ROWB
                               + ((lane & 8) ? 16 : 0));

    float q2[2][2] = {}, qb[2][2] = {};

    for (int pj = 0; pj < 4; pj++) {
        int jt0 = 4 * pj, jt3 = jt0 + 3;
        float acc[4][2][4][4] = {};
        lg_stage(sb, 0, c, m0, jt0, 0, tid);
        CPA_COMMIT;
        for (int kt = 0; kt <= jt3; kt++) {
            if (kt < jt3) {
                lg_stage(sb, (kt + 1) & 1, c, m0, jt0, kt + 1, tid);
                CPA_COMMIT;
                CPA_WAIT1;
            } else {
                CPA_WAIT0;
            }
            __syncthreads();
            uint32_t s0 = sb + (uint32_t)((kt & 1) * LG5_STAGE);
            uint32_t aH = s0 + LG5_SAH + aoff, aL = s0 + LG5_SAL + aoff;
            uint32_t bH0 = s0 + LG5_SBH + boff, bL0 = s0 + LG5_SBL + boff;
#pragma unroll
            for (int ks = 0; ks < 4; ks++) {
                uint32_t ah[2][4], al[2][4];
                ldsm4(ah[0], aH + ks * 32);
                ldsm4(ah[1], aH + 16 * LG5_ROWB + ks * 32);
                ldsm4(al[0], aL + ks * 32);
                ldsm4(al[1], aL + 16 * LG5_ROWB + ks * 32);
#pragma unroll
                for (int t = 0; t < 4; t++) {
                    if (kt > jt0 + t) continue;
                    uint32_t bh[8], bl[8];
                    ldsm4(&bh[0], bH0 + t * 9216 + ks * 32);
                    ldsm4(&bh[4], bH0 + t * 9216 + 16 * LG5_ROWB + ks * 32);
                    ldsm4(&bl[0], bL0 + t * 9216 + ks * 32);
                    ldsm4(&bl[4], bL0 + t * 9216 + 16 * LG5_ROWB + ks * 32);
#pragma unroll
                    for (int ms = 0; ms < 2; ms++)
#pragma unroll
                        for (int nt = 0; nt < 4; nt++) {
                            float* d = acc[t][ms][nt];
                            mma16816(d, ah[ms], &bh[nt * 2]);
                            mma16816(d, al[ms], &bh[nt * 2]);
                            mma16816(d, ah[ms], &bl[nt * 2]);
                        }
                }
            }
            __syncthreads();
        }
#pragma unroll
        for (int t = 0; t < 4; t++) {
            int jt = jt0 + t;
#pragma unroll
            for (int ms = 0; ms < 2; ms++)
#pragma unroll
                for (int nt = 0; nt < 4; nt++) {
                    int jc = jt * 64 + wn * 32 + nt * 8 + 2 * (lane & 3);
                    float s0 = g_s[c][jc], s1 = g_s[c][jc + 1];
                    float* d = acc[t][ms][nt];
                    q2[ms][0] += d[0] * d[0] + d[1] * d[1];
                    qb[ms][0] += d[0] * s0 + d[1] * s1;
                    q2[ms][1] += d[2] * d[2] + d[3] * d[3];
                    qb[ms][1] += d[2] * s0 + d[3] * s1;
                }
        }
    }

    __syncthreads();
    float* rq = (float*)smem;
    float* rb = (float*)(smem + 4096);
    int slot = wn * 4 + (lane & 3);
    int g = lane >> 2;
#pragma unroll
    for (int ms = 0; ms < 2; ms++)
#pragma unroll
        for (int go = 0; go < 2; go++) {
            int row = wm * 32 + ms * 16 + go * 8 + g;
            rq[row * 8 + slot] = q2[ms][go];
            rb[row * 8 + slot] = qb[ms][go];
        }
    __syncthreads();
    if (tid < 128) {
        float q2r = 0.f, qbr = 0.f;
#pragma unroll
        for (int t = 0; t < 8; t++) { q2r += rq[tid * 8 + t]; qbr += rb[tid * 8 + t]; }
        int row = m0 + tid;
        float dq = g_nx[row] - 2.f * g_xm[row][c] + g_mmc[c];
        float qm = q2r - 2.f * qbr + g_ssc[c];
        out[(size_t)row * CLS + c] = -0.9f * qm - 0.1f * dq;
    }
}

// ---------------- launch ----------------
extern "C" void kernel_launch(void* const* d_in, const int* in_sizes, int n_in,
                              void* d_out, int out_size) {
    const float* X     = (const float*)d_in[0];
    const int*   y     = (const int*)d_in[1];
    const float* Xq    = (const float*)d_in[2];
    const float* m     = (const float*)d_in[3];
    const float* kappa = (const float*)d_in[4];
    const float* nu    = (const float*)d_in[5];
    const float* td    = (const float*)d_in[6];
    const float* tl    = (const float*)d_in[7];
    float* out = (float*)d_out;

    cudaFuncSetAttribute(k_logits_mma, cudaFuncAttributeMaxDynamicSharedMemorySize, LG5_SMEM);

    k_stats1<<<dim3(8, 8), 128>>>(X, y);
    k_sort_params<<<1, 32>>>(y, kappa, nu);
    k_mu<<<dim3(4, CLS), 256>>>(m);
    k_cvt_xq<<<16384, 256>>>(Xq);
    k_buildL<<<D, 256>>>(td, tl);
    k_base<<<dim3(NT, NT), 256>>>(m);
    k_nxm<<<MQ / 8, 256>>>(Xq);

    k_sigma_mma<<<dim3(8, 16, CLS), 256>>>(X);
    k_chol_diag0<<<CLS, 256>>>();
    for (int kb = 0; kb < NT - 1; kb++) {
        int T = NT - 1 - kb;
        k_pgemm<<<dim3(T, CLS), 128>>>(kb);
        k_trail_mma<<<dim3(T * (T + 1) / 2, CLS), 128>>>(kb);
    }
    for (int s = 0; s < 4; s++) {
        int h = 64 << s;
        int tpr = h >> 6;
        int tiles = (D / (2 * h)) * tpr * tpr;
        k_tri1<<<dim3(tiles, CLS), 128>>>(h);
        k_tri2<<<dim3(tiles, CLS), 128>>>(h);
    }
    k_svec<<<dim3(D / 8, CLS), 256>>>();
    k_scalars<<<CLS, 256>>>();
    k_logits_mma<<<dim3(MQ / 128, CLS), 256, LG5_SMEM>>>(out);
}

// round 17
// speedup vs baseline: 1.1630x; 1.1630x over previous
#include <cuda_runtime.h>
#include <cuda_bf16.h>
#include <cuda_fp16.h>
#include <math.h>
#include <stdint.h>

#define D      1024
#define CLS    16
#define NSAMP  4096
#define MQ     4096
#define NT     16

__device__ float g_Sigma[CLS][D][D];
__device__ float g_V[CLS][D][D];
__device__ float g_T1[CLS][262144];
__device__ float g_Base[D][D];
__device__ float g_L[D][D];
__device__ float g_part[8][CLS][D];
__device__ float g_mu[CLS][D];
__device__ float g_s[CLS][D];
__device__ float g_nx[MQ];
__device__ float g_xm[MQ][CLS];
__device__ float g_ssc[CLS];
__device__ float g_mmc[CLS];
__device__ int   g_cnt[CLS];
__device__ int   g_cntp[8][CLS];
__device__ int   g_start[CLS];
__device__ int   g_idx[NSAMP];
__device__ float g_kap;
__device__ float g_coef[CLS];
__device__ float g_invscale[CLS];

__device__ __half g_Xqh[MQ][D];
__device__ __half g_Vh[CLS][D][D];

__device__ __forceinline__ uint32_t smem_u32(const void* p) {
    uint32_t a;
    asm("{ .reg .u64 t; cvta.to.shared.u64 t, %1; cvt.u32.u64 %0, t; }" : "=r"(a) : "l"(p));
    return a;
}
__device__ __forceinline__ void ldsm4(uint32_t* r, uint32_t a) {
    asm volatile("ldmatrix.sync.aligned.m8n8.x4.shared.b16 {%0,%1,%2,%3}, [%4];"
                 : "=r"(r[0]), "=r"(r[1]), "=r"(r[2]), "=r"(r[3]) : "r"(a));
}
__device__ __forceinline__ void mma16816h(float* d, const uint32_t* a, const uint32_t* b) {
    asm volatile(
        "mma.sync.aligned.m16n8k16.row.col.f32.f16.f16.f32 "
        "{%0,%1,%2,%3}, {%4,%5,%6,%7}, {%8,%9}, {%0,%1,%2,%3};"
        : "+f"(d[0]), "+f"(d[1]), "+f"(d[2]), "+f"(d[3])
        : "r"(a[0]), "r"(a[1]), "r"(a[2]), "r"(a[3]), "r"(b[0]), "r"(b[1]));
}
__device__ __forceinline__ void mma_tf32(float* d, const uint32_t* a, const uint32_t* b) {
    asm volatile(
        "mma.sync.aligned.m16n8k8.row.col.f32.tf32.tf32.f32 "
        "{%0,%1,%2,%3}, {%4,%5,%6,%7}, {%8,%9}, {%0,%1,%2,%3};"
        : "+f"(d[0]), "+f"(d[1]), "+f"(d[2]), "+f"(d[3])
        : "r"(a[0]), "r"(a[1]), "r"(a[2]), "r"(a[3]), "r"(b[0]), "r"(b[1]));
}
__device__ __forceinline__ float tf32_rn(float x) {
    uint32_t u;
    asm("cvt.rna.tf32.f32 %0, %1;" : "=r"(u) : "f"(x));
    return __uint_as_float(u);
}
__device__ __forceinline__ void cpa16(uint32_t s, const void* g) {
    asm volatile("{ .reg .u64 gg; cvta.to.global.u64 gg, %1; cp.async.ca.shared.global [%0], [gg], 16; }"
                 :: "r"(s), "l"(g) : "memory");
}
#define CPA_COMMIT asm volatile("cp.async.commit_group;" ::: "memory")
#define CPA_WAIT1  asm volatile("cp.async.wait_group 1;" ::: "memory")
#define CPA_WAIT0  asm volatile("cp.async.wait_group 0;" ::: "memory")
#define FB(x) (__float_as_uint(x))
#define MMA3(d, ah, bh, al, bl) { mma_tf32(d, ah, bh); mma_tf32(d, ah, bl); mma_tf32(d, al, bh); }

__device__ __forceinline__ void writeV(int c, int i, int j, float v) {
    g_V[c][i][j] = v;
    g_Vh[c][i][j] = __float2half(v);
}

// race-free row-owner Cholesky factor (lower) + column-wise inverse -> writeV
__device__ __forceinline__ void chol_factor_invert(float (*Ds)[65], int tid, int c, int base) {
    for (int j = 0; j < 64; j++) {
        float s = sqrtf(Ds[j][j]);
        if (tid > j && tid < 64) Ds[tid][j] /= s;
        __syncthreads();
        if (tid == j) Ds[j][j] = s;
        if (tid > j && tid < 64) {
            float lij = Ds[tid][j];
            for (int kc = j + 1; kc <= tid; kc++) Ds[tid][kc] -= lij * Ds[kc][j];
        }
        __syncthreads();
    }
    if (tid < 64) {
        int j = tid;
        float x[64];
#pragma unroll
        for (int i = 0; i < 64; i++) {
            float tv = (i == j) ? 1.0f : 0.0f;
#pragma unroll
            for (int k = 0; k < i; k++) tv -= Ds[i][k] * x[k];
            x[i] = tv / Ds[i][i];
        }
#pragma unroll
        for (int i = 0; i < 64; i++) writeV(c, base + i, base + j, x[i]);
    }
}

// ---------------- stats ----------------
__global__ void k_stats1(const float* __restrict__ X, const int* __restrict__ y) {
    __shared__ int sy[512];
    int tid = threadIdx.x;
    int r0 = blockIdx.y * 512;
    for (int n = tid; n < 512; n += 128) sy[n] = y[r0 + n];
    __syncthreads();
    int k = blockIdx.x * 128 + tid;
    float acc[CLS];
#pragma unroll
    for (int c = 0; c < CLS; c++) acc[c] = 0.f;
    for (int n = 0; n < 512; n++) {
        float v = X[(size_t)(r0 + n) * D + k];
        int cls = sy[n];
#pragma unroll
        for (int c = 0; c < CLS; c++) acc[c] += (cls == c) ? v : 0.f;
    }
#pragma unroll
    for (int c = 0; c < CLS; c++) g_part[blockIdx.y][c][k] = acc[c];
    if (blockIdx.x == 0) {
        __shared__ int scnt[CLS];
        if (tid < CLS) scnt[tid] = 0;
        __syncthreads();
        for (int n = tid; n < 512; n += 128) atomicAdd(&scnt[sy[n]], 1);
        __syncthreads();
        if (tid < CLS) g_cntp[blockIdx.y][tid] = scnt[tid];
    }
}
__global__ void k_sort_params(const int* __restrict__ y, const float* __restrict__ kappa,
                              const float* __restrict__ nu) {
    __shared__ int s_start[CLS];
    int lane = threadIdx.x;
    if (lane == 0) {
        int s = 0;
        for (int c = 0; c < CLS; c++) {
            int t = 0;
            for (int r = 0; r < 8; r++) t += g_cntp[r][c];
            g_cnt[c] = t; g_start[c] = s; s_start[c] = s; s += t;
        }
        float kap = fabsf(kappa[0]) + 1e-6f;
        g_kap = kap;
        float nu_ = fmaxf(nu[0], (float)(D - 1) + 1e-6f);
        for (int c = 0; c < CLS; c++) {
            float Nj = (float)g_cnt[c];
            g_coef[c] = kap + Nj;
            g_invscale[c] = 1.0f / (nu_ + Nj + (float)D + 2.0f);
        }
    }
    __syncthreads();
    int off[CLS];
#pragma unroll
    for (int c = 0; c < CLS; c++) off[c] = s_start[c];
    unsigned below = (1u << lane) - 1u;
    for (int n0 = 0; n0 < NSAMP; n0 += 32) {
        int v = y[n0 + lane];
#pragma unroll
        for (int c = 0; c < CLS; c++) {
            unsigned m = __ballot_sync(0xffffffffu, v == c);
            if (v == c) g_idx[off[c] + __popc(m & below)] = n0 + lane;
            off[c] += __popc(m);
        }
    }
}
__global__ void k_mu(const float* __restrict__ m) {
    int c = blockIdx.y;
    int k = blockIdx.x * blockDim.x + threadIdx.x;
    float s = 0.f;
#pragma unroll
    for (int r = 0; r < 8; r++) s += g_part[r][c][k];
    g_mu[c][k] = (g_kap * m[k] + s) / g_coef[c];
}
__global__ void k_buildL(const float* __restrict__ td, const float* __restrict__ tl) {
    int i = blockIdx.x;
    for (int k = threadIdx.x; k < D; k += blockDim.x) {
        float v;
        if (k < i) v = tl[(size_t)i * D + k];
        else if (k == i) v = fabsf(td[i]);
        else v = 0.f;
        g_L[i][k] = v;
    }
}

// ---------------- Base = L L^T + kap m m^T (triangular skip) ----------------
__global__ __launch_bounds__(256) void k_base(const float* __restrict__ m) {
    __shared__ float As[16][65];
    __shared__ float Bs[16][65];
    int i0 = blockIdx.x * 64, j0 = blockIdx.y * 64;
    int tid = threadIdx.x, tx = tid & 15, ty = tid >> 4;
    float acc[4][4] = {};
    int kend = ((i0 < j0) ? i0 : j0) + 64;
    for (int k0 = 0; k0 < kend; k0 += 16) {
#pragma unroll
        for (int t = 0; t < 4; t++) {
            int idx = tid + 256 * t;
            int ii = idx >> 4, kk = idx & 15;
            As[kk][ii] = g_L[i0 + ii][k0 + kk];
            Bs[kk][ii] = g_L[j0 + ii][k0 + kk];
        }
        __syncthreads();
#pragma unroll
        for (int kk = 0; kk < 16; kk++) {
            float a[4], b[4];
#pragma unroll
            for (int q = 0; q < 4; q++) a[q] = As[kk][4 * ty + q];
#pragma unroll
            for (int q = 0; q < 4; q++) b[q] = Bs[kk][4 * tx + q];
#pragma unroll
            for (int p = 0; p < 4; p++)
#pragma unroll
                for (int q = 0; q < 4; q++) acc[p][q] += a[p] * b[q];
        }
        __syncthreads();
    }
    float kap = g_kap;
#pragma unroll
    for (int p = 0; p < 4; p++) {
        int i = i0 + 4 * ty + p;
        float mi = m[i];
#pragma unroll
        for (int q = 0; q < 4; q++) {
            int j = j0 + 4 * tx + q;
            g_Base[i][j] = acc[p][q] + kap * mi * m[j];
        }
    }
}

// ---------------- Sigma = (Base + S - coef*mu mu^T)*invscale (tf32-split mma) -----
__global__ __launch_bounds__(256) void k_sigma_mma(const float* __restrict__ X) {
    __shared__ float Ah[16][136], Al[16][136];
    __shared__ float Bh[16][72],  Bl[16][72];
    int c = blockIdx.z;
    int i0 = blockIdx.x * 128, j0 = blockIdx.y * 64;
    int tid = threadIdx.x, lane = tid & 31, wid = tid >> 5;
    int wm = wid >> 1, wn = wid & 1;
    int r = lane >> 2, q = lane & 3;
    int cnt = g_cnt[c], start = g_start[c];
    float acc[2][4][4] = {};
    int kmax = (cnt + 15) & ~15;
    for (int k0 = 0; k0 < kmax; k0 += 16) {
        __syncthreads();
#pragma unroll
        for (int t = 0; t < 8; t++) {
            int e = tid + 256 * t;
            int kk = e >> 7, col = e & 127;
            int krow = k0 + kk;
            float v = (krow < cnt) ? X[(size_t)g_idx[start + krow] * D + i0 + col] : 0.f;
            float h = tf32_rn(v);
            Ah[kk][col] = h; Al[kk][col] = tf32_rn(v - h);
        }
#pragma unroll
        for (int t = 0; t < 4; t++) {
            int e = tid + 256 * t;
            int kk = e >> 6, col = e & 63;
            int krow = k0 + kk;
            float v = (krow < cnt) ? X[(size_t)g_idx[start + krow] * D + j0 + col] : 0.f;
            float h = tf32_rn(v);
            Bh[kk][col] = h; Bl[kk][col] = tf32_rn(v - h);
        }
        __syncthreads();
#pragma unroll
        for (int ks = 0; ks < 2; ks++) {
            int k8 = ks * 8;
            uint32_t ah[2][4], al[2][4], bh[4][2], bl[4][2];
#pragma unroll
            for (int ms = 0; ms < 2; ms++) {
                int mb = wm * 32 + ms * 16;
                ah[ms][0] = FB(Ah[k8 + q][mb + r]);     ah[ms][1] = FB(Ah[k8 + q][mb + 8 + r]);
                ah[ms][2] = FB(Ah[k8 + 4 + q][mb + r]); ah[ms][3] = FB(Ah[k8 + 4 + q][mb + 8 + r]);
                al[ms][0] = FB(Al[k8 + q][mb + r]);     al[ms][1] = FB(Al[k8 + q][mb + 8 + r]);
                al[ms][2] = FB(Al[k8 + 4 + q][mb + r]); al[ms][3] = FB(Al[k8 + 4 + q][mb + 8 + r]);
            }
#pragma unroll
            for (int nt = 0; nt < 4; nt++) {
                int nb = wn * 32 + nt * 8;
                bh[nt][0] = FB(Bh[k8 + q][nb + r]); bh[nt][1] = FB(Bh[k8 + 4 + q][nb + r]);
                bl[nt][0] = FB(Bl[k8 + q][nb + r]); bl[nt][1] = FB(Bl[k8 + 4 + q][nb + r]);
            }
#pragma unroll
            for (int ms = 0; ms < 2; ms++)
#pragma unroll
                for (int nt = 0; nt < 4; nt++)
                    MMA3(acc[ms][nt], ah[ms], bh[nt], al[ms], bl[nt]);
        }
    }
    float coef = g_coef[c], inv = g_invscale[c];
#pragma unroll
    for (int ms = 0; ms < 2; ms++)
#pragma unroll
        for (int nt = 0; nt < 4; nt++) {
            int i = i0 + wm * 32 + ms * 16 + r;
            int j = j0 + wn * 32 + nt * 8 + 2 * q;
            float* d = acc[ms][nt];
            float mui = g_mu[c][i], mui8 = g_mu[c][i + 8];
            float mj0 = g_mu[c][j], mj1 = g_mu[c][j + 1];
            g_Sigma[c][i][j]         = (g_Base[i][j]         + d[0] - coef * mui  * mj0) * inv;
            g_Sigma[c][i][j + 1]     = (g_Base[i][j + 1]     + d[1] - coef * mui  * mj1) * inv;
            g_Sigma[c][i + 8][j]     = (g_Base[i + 8][j]     + d[2] - coef * mui8 * mj0) * inv;
            g_Sigma[c][i + 8][j + 1] = (g_Base[i + 8][j + 1] + d[3] - coef * mui8 * mj1) * inv;
        }
}

// ---------------- initial diag ----------------
__global__ __launch_bounds__(256) void k_chol_diag0() {
    __shared__ float Ds[64][65];
    int c = blockIdx.x;
    int tid = threadIdx.x;
    for (int e = tid; e < 4096; e += 256)
        Ds[e >> 6][e & 63] = g_Sigma[c][e >> 6][e & 63];
    __syncthreads();
    chol_factor_invert(Ds, tid, c, 0);
}

// ---------------- panel P = A21 * invL11^T (tf32) ----------------
__global__ __launch_bounds__(128) void k_pgemm(int kb) {
    __shared__ float Ah[64][20], Al[64][20], Bh[64][20], Bl[64][20];
    int c = blockIdx.y;
    int kbase = kb * 64;
    int i0 = kbase + 64 + blockIdx.x * 64;
    int tid = threadIdx.x, lane = tid & 31, wid = tid >> 5;
    int wy = wid >> 1, wx = wid & 1;
    int r = lane >> 2, q = lane & 3;
    float acc[2][4][4] = {};
    for (int k0 = 0; k0 < 64; k0 += 16) {
        __syncthreads();
#pragma unroll
        for (int t = 0; t < 8; t++) {
            int e = tid + 128 * t;
            int i = e >> 4, k = e & 15;
            float va = g_Sigma[c][i0 + i][kbase + k0 + k];
            float h = tf32_rn(va);
            Ah[i][k] = h; Al[i][k] = tf32_rn(va - h);
            float vb = g_V[c][kbase + i][kbase + k0 + k];
            h = tf32_rn(vb);
            Bh[i][k] = h; Bl[i][k] = tf32_rn(vb - h);
        }
        __syncthreads();
#pragma unroll
        for (int ks = 0; ks < 2; ks++) {
            int k8 = ks * 8;
            uint32_t ah[2][4], al[2][4], bh[4][2], bl[4][2];
#pragma unroll
            for (int ms = 0; ms < 2; ms++) {
                int mb = wy * 32 + ms * 16;
                ah[ms][0] = FB(Ah[mb + r][k8 + q]);     ah[ms][1] = FB(Ah[mb + 8 + r][k8 + q]);
                ah[ms][2] = FB(Ah[mb + r][k8 + 4 + q]); ah[ms][3] = FB(Ah[mb + 8 + r][k8 + 4 + q]);
                al[ms][0] = FB(Al[mb + r][k8 + q]);     al[ms][1] = FB(Al[mb + 8 + r][k8 + q]);
                al[ms][2] = FB(Al[mb + r][k8 + 4 + q]); al[ms][3] = FB(Al[mb + 8 + r][k8 + 4 + q]);
            }
#pragma unroll
            for (int nt = 0; nt < 4; nt++) {
                int nb = wx * 32 + nt * 8;
                bh[nt][0] = FB(Bh[nb + r][k8 + q]); bh[nt][1] = FB(Bh[nb + r][k8 + 4 + q]);
                bl[nt][0] = FB(Bl[nb + r][k8 + q]); bl[nt][1] = FB(Bl[nb + r][k8 + 4 + q]);
            }
#pragma unroll
            for (int ms = 0; ms < 2; ms++)
#pragma unroll
                for (int nt = 0; nt < 4; nt++)
                    MMA3(acc[ms][nt], ah[ms], bh[nt], al[ms], bl[nt]);
        }
    }
    __syncthreads();
#pragma unroll
    for (int ms = 0; ms < 2; ms++)
#pragma unroll
        for (int nt = 0; nt < 4; nt++) {
            int i = i0 + wy * 32 + ms * 16 + r;
            int j = kbase + wx * 32 + nt * 8 + 2 * q;
            float* d = acc[ms][nt];
            g_Sigma[c][i][j]         = d[0];
            g_Sigma[c][i][j + 1]     = d[1];
            g_Sigma[c][i + 8][j]     = d[2];
            g_Sigma[c][i + 8][j + 1] = d[3];
        }
}

// ---------------- trailing syrk (tf32) + fused next-diag (race-free fast) ---------
__global__ __launch_bounds__(128) void k_trail_mma(int kb) {
    __shared__ char buf[20480];
    float (*Ah)[20] = (float(*)[20])buf;
    float (*Al)[20] = (float(*)[20])(buf + 5120);
    float (*Bh)[20] = (float(*)[20])(buf + 10240);
    float (*Bl)[20] = (float(*)[20])(buf + 15360);
    int c = blockIdx.y;
    int pidx = blockIdx.x;
    int ti = kb + 1;
    while (pidx >= ti - kb) { pidx -= ti - kb; ti++; }
    int tj = kb + 1 + pidx;
    int i0 = ti * 64, j0 = tj * 64, kbase = kb * 64;
    int tid = threadIdx.x, lane = tid & 31, wid = tid >> 5;
    int wy = wid >> 1, wx = wid & 1;
    int r = lane >> 2, q = lane & 3;
    float acc[2][4][4] = {};
    for (int k0 = 0; k0 < 64; k0 += 16) {
        __syncthreads();
#pragma unroll
        for (int t = 0; t < 8; t++) {
            int e = tid + 128 * t;
            int i = e >> 4, k = e & 15;
            float va = g_Sigma[c][i0 + i][kbase + k0 + k];
            float h = tf32_rn(va);
            Ah[i][k] = h; Al[i][k] = tf32_rn(va - h);
            float vb = g_Sigma[c][j0 + i][kbase + k0 + k];
            h = tf32_rn(vb);
            Bh[i][k] = h; Bl[i][k] = tf32_rn(vb - h);
        }
        __syncthreads();
#pragma unroll
        for (int ks = 0; ks < 2; ks++) {
            int k8 = ks * 8;
            uint32_t ah[2][4], al[2][4], bh[4][2], bl[4][2];
#pragma unroll
            for (int ms = 0; ms < 2; ms++) {
                int mb = wy * 32 + ms * 16;
                ah[ms][0] = FB(Ah[mb + r][k8 + q]);     ah[ms][1] = FB(Ah[mb + 8 + r][k8 + q]);
                ah[ms][2] = FB(Ah[mb + r][k8 + 4 + q]); ah[ms][3] = FB(Ah[mb + 8 + r][k8 + 4 + q]);
                al[ms][0] = FB(Al[mb + r][k8 + q]);     al[ms][1] = FB(Al[mb + 8 + r][k8 + q]);
                al[ms][2] = FB(Al[mb + r][k8 + 4 + q]); al[ms][3] = FB(Al[mb + 8 + r][k8 + 4 + q]);
            }
#pragma unroll
            for (int nt = 0; nt < 4; nt++) {
                int nb = wx * 32 + nt * 8;
                bh[nt][0] = FB(Bh[nb + r][k8 + q]); bh[nt][1] = FB(Bh[nb + r][k8 + 4 + q]);
                bl[nt][0] = FB(Bl[nb + r][k8 + q]); bl[nt][1] = FB(Bl[nb + r][k8 + 4 + q]);
            }
#pragma unroll
            for (int ms = 0; ms < 2; ms++)
#pragma unroll
                for (int nt = 0; nt < 4; nt++)
                    MMA3(acc[ms][nt], ah[ms], bh[nt], al[ms], bl[nt]);
        }
    }
    __syncthreads();
#pragma unroll
    for (int ms = 0; ms < 2; ms++)
#pragma unroll
        for (int nt = 0; nt < 4; nt++) {
            int i = i0 + wy * 32 + ms * 16 + r;
            int j = j0 + wx * 32 + nt * 8 + 2 * q;
            float* d = acc[ms][nt];
            g_Sigma[c][i][j]         -= d[0];
            g_Sigma[c][i][j + 1]     -= d[1];
            g_Sigma[c][i + 8][j]     -= d[2];
            g_Sigma[c][i + 8][j + 1] -= d[3];
        }
    if (blockIdx.x == 0) {
        int base = (kb + 1) * 64;
        __syncthreads();
        float (*Ds)[65] = (float(*)[65])buf;
        for (int e = tid; e < 4096; e += 128)
            Ds[e >> 6][e & 63] = g_Sigma[c][base + (e >> 6)][base + (e & 63)];
        __syncthreads();
        chol_factor_invert(Ds, tid, c, base);
    }
}

// ---------------- recursive triinv stage GEMM 1: T1 = A21 * V11 -------------------
__global__ __launch_bounds__(128) void k_tri1(int h) {
    __shared__ float Ah[64][20], Al[64][20], Bh[16][72], Bl[16][72];
    int c = blockIdx.y;
    int tpr = h >> 6, t2 = tpr * tpr;
    int p = blockIdx.x / t2;
    int rem = blockIdx.x % t2;
    int mi = rem / tpr, ni = rem % tpr;
    int base = p * 2 * h;
    int r0 = base + h + mi * 64;
    int n0 = ni * 64;
    int tid = threadIdx.x, lane = tid & 31, wid = tid >> 5;
    int wy = wid >> 1, wx = wid & 1;
    int r = lane >> 2, q = lane & 3;
    float acc[2][4][4] = {};
    for (int k0 = 0; k0 < h; k0 += 16) {
        __syncthreads();
        for (int t = 0; t < 8; t++) {
            int e = tid + 128 * t;
            {
                int i = e >> 4, k = e & 15;
                float v = g_Sigma[c][r0 + i][base + k0 + k];
                float hh = tf32_rn(v);
                Ah[i][k] = hh; Al[i][k] = tf32_rn(v - hh);
            }
            {
                int k = e >> 6, j = e & 63;
                float v = ((k0 + k) >= (n0 + j)) ? g_V[c][base + k0 + k][base + n0 + j] : 0.f;
                float hh = tf32_rn(v);
                Bh[k][j] = hh; Bl[k][j] = tf32_rn(v - hh);
            }
        }
        __syncthreads();
#pragma unroll
        for (int ks = 0; ks < 2; ks++) {
            int k8 = ks * 8;
            uint32_t ah[2][4], al[2][4], bh[4][2], bl[4][2];
#pragma unroll
            for (int ms = 0; ms < 2; ms++) {
                int mb = wy * 32 + ms * 16;
                ah[ms][0] = FB(Ah[mb + r][k8 + q]);     ah[ms][1] = FB(Ah[mb + 8 + r][k8 + q]);
                ah[ms][2] = FB(Ah[mb + r][k8 + 4 + q]); ah[ms][3] = FB(Ah[mb + 8 + r][k8 + 4 + q]);
                al[ms][0] = FB(Al[mb + r][k8 + q]);     al[ms][1] = FB(Al[mb + 8 + r][k8 + q]);
                al[ms][2] = FB(Al[mb + r][k8 + 4 + q]); al[ms][3] = FB(Al[mb + 8 + r][k8 + 4 + q]);
            }
#pragma unroll
            for (int nt = 0; nt < 4; nt++) {
                int nb = wx * 32 + nt * 8;
                bh[nt][0] = FB(Bh[k8 + q][nb + r]); bh[nt][1] = FB(Bh[k8 + 4 + q][nb + r]);
                bl[nt][0] = FB(Bl[k8 + q][nb + r]); bl[nt][1] = FB(Bl[k8 + 4 + q][nb + r]);
            }
#pragma unroll
            for (int ms = 0; ms < 2; ms++)
#pragma unroll
                for (int nt = 0; nt < 4; nt++)
                    MMA3(acc[ms][nt], ah[ms], bh[nt], al[ms], bl[nt]);
        }
    }
    int pb = p * h * h;
#pragma unroll
    for (int ms = 0; ms < 2; ms++)
#pragma unroll
        for (int nt = 0; nt < 4; nt++) {
            int il = mi * 64 + wy * 32 + ms * 16 + r;
            int jl = n0 + wx * 32 + nt * 8 + 2 * q;
            float* d = acc[ms][nt];
            g_T1[c][pb + il * h + jl]           = d[0];
            g_T1[c][pb + il * h + jl + 1]       = d[1];
            g_T1[c][pb + (il + 8) * h + jl]     = d[2];
            g_T1[c][pb + (il + 8) * h + jl + 1] = d[3];
        }
}

// ---------------- stage GEMM 2: V21 = -V22 * T1 (writes V + fp16) -----------------
__global__ __launch_bounds__(128) void k_tri2(int h) {
    __shared__ float Ah[64][20], Al[64][20], Bh[16][72], Bl[16][72];
    int c = blockIdx.y;
    int tpr = h >> 6, t2 = tpr * tpr;
    int p = blockIdx.x / t2;
    int rem = blockIdx.x % t2;
    int mi = rem / tpr, ni = rem % tpr;
    int base = p * 2 * h;
    int rv = base + h;
    int n0 = ni * 64;
    int tid = threadIdx.x, lane = tid & 31, wid = tid >> 5;
    int wy = wid >> 1, wx = wid & 1;
    int r = lane >> 2, q = lane & 3;
    int pb = p * h * h;
    float acc[2][4][4] = {};
    for (int k0 = 0; k0 < h; k0 += 16) {
        __syncthreads();
        for (int t = 0; t < 8; t++) {
            int e = tid + 128 * t;
            {
                int i = e >> 4, k = e & 15;
                float v = ((mi * 64 + i) >= (k0 + k)) ? g_V[c][rv + mi * 64 + i][rv + k0 + k] : 0.f;
                float hh = tf32_rn(v);
                Ah[i][k] = hh; Al[i][k] = tf32_rn(v - hh);
            }
            {
                int k = e >> 6, j = e & 63;
                float v = g_T1[c][pb + (k0 + k) * h + n0 + j];
                float hh = tf32_rn(v);
                Bh[k][j] = hh; Bl[k][j] = tf32_rn(v - hh);
            }
        }
        __syncthreads();
#pragma unroll
        for (int ks = 0; ks < 2; ks++) {
            int k8 = ks * 8;
            uint32_t ah[2][4], al[2][4], bh[4][2], bl[4][2];
#pragma unroll
            for (int ms = 0; ms < 2; ms++) {
                int mb = wy * 32 + ms * 16;
                ah[ms][0] = FB(Ah[mb + r][k8 + q]);     ah[ms][1] = FB(Ah[mb + 8 + r][k8 + q]);
                ah[ms][2] = FB(Ah[mb + r][k8 + 4 + q]); ah[ms][3] = FB(Ah[mb + 8 + r][k8 + 4 + q]);
                al[ms][0] = FB(Al[mb + r][k8 + q]);     al[ms][1] = FB(Al[mb + 8 + r][k8 + q]);
                al[ms][2] = FB(Al[mb + r][k8 + 4 + q]); al[ms][3] = FB(Al[mb + 8 + r][k8 + 4 + q]);
            }
#pragma unroll
            for (int nt = 0; nt < 4; nt++) {
                int nb = wx * 32 + nt * 8;
                bh[nt][0] = FB(Bh[k8 + q][nb + r]); bh[nt][1] = FB(Bh[k8 + 4 + q][nb + r]);
                bl[nt][0] = FB(Bl[k8 + q][nb + r]); bl[nt][1] = FB(Bl[k8 + 4 + q][nb + r]);
            }
#pragma unroll
            for (int ms = 0; ms < 2; ms++)
#pragma unroll
                for (int nt = 0; nt < 4; nt++)
                    MMA3(acc[ms][nt], ah[ms], bh[nt], al[ms], bl[nt]);
        }
    }
#pragma unroll
    for (int ms = 0; ms < 2; ms++)
#pragma unroll
        for (int nt = 0; nt < 4; nt++) {
            int ig = rv + mi * 64 + wy * 32 + ms * 16 + r;
            int jg = base + n0 + wx * 32 + nt * 8 + 2 * q;
            float* d = acc[ms][nt];
            writeV(c, ig, jg, -d[0]);
            writeV(c, ig, jg + 1, -d[1]);
            writeV(c, ig + 8, jg, -d[2]);
            writeV(c, ig + 8, jg + 1, -d[3]);
        }
}

// ---------------- conversions / small vec kernels ----------------
__global__ void k_cvt_xq(const float* __restrict__ Xq) {
    int i = blockIdx.x * 256 + threadIdx.x;
    g_Xqh[0][i] = __float2half(Xq[i]);
}
__global__ void k_svec() {
    int c = blockIdx.y;
    int warp = threadIdx.x >> 5, lane = threadIdx.x & 31;
    int row = blockIdx.x * 8 + warp;
    float acc = 0.f;
    for (int k = lane; k <= row; k += 32) acc += g_V[c][row][k] * g_mu[c][k];
    for (int o = 16; o > 0; o >>= 1) acc += __shfl_down_sync(0xffffffffu, acc, o);
    if (lane == 0) g_s[c][row] = acc;
}
__global__ void k_scalars() {
    int c = blockIdx.x;
    __shared__ float r1[256], r2[256];
    float a = 0.f, b = 0.f;
    for (int k = threadIdx.x; k < D; k += 256) {
        float sv = g_s[c][k];  a += sv * sv;
        float mv = g_mu[c][k]; b += mv * mv;
    }
    r1[threadIdx.x] = a; r2[threadIdx.x] = b;
    __syncthreads();
    for (int o = 128; o > 0; o >>= 1) {
        if (threadIdx.x < o) { r1[threadIdx.x] += r1[threadIdx.x + o]; r2[threadIdx.x] += r2[threadIdx.x + o]; }
        __syncthreads();
    }
    if (threadIdx.x == 0) { g_ssc[c] = r1[0]; g_mmc[c] = r2[0]; }
}
__global__ void k_nxm(const float* __restrict__ Xq) {
    int warp = threadIdx.x >> 5, lane = threadIdx.x & 31;
    int row = blockIdx.x * 8 + warp;
    float acc[CLS + 1];
#pragma unroll
    for (int c = 0; c <= CLS; c++) acc[c] = 0.f;
    for (int k = lane; k < D; k += 32) {
        float v = Xq[(size_t)row * D + k];
        acc[CLS] += v * v;
#pragma unroll
        for (int c = 0; c < CLS; c++) acc[c] += v * g_mu[c][k];
    }
#pragma unroll
    for (int c = 0; c <= CLS; c++) {
        float a = acc[c];
        for (int o = 16; o > 0; o >>= 1) a += __shfl_down_sync(0xffffffffu, a, o);
        if (lane == 0) {
            if (c < CLS) g_xm[row][c] = a;
            else g_nx[row] = a;
        }
    }
}

// ====== logits: fp16 single-product mma, jt-paired + cp.async double-buffered =====
#define LGH_ROWB  144
#define LGH_SA    0
#define LGH_SB    18432
#define LGH_STAGE 36864
#define LGH_SMEM  73728

__device__ __forceinline__ void lg_stage(uint32_t sb, int s, int c, int m0, int jt0,
                                         int kt, int tid) {
    uint32_t base = sb + (uint32_t)(s * LGH_STAGE);
#pragma unroll
    for (int t = 0; t < 4; t++) {
        int idx = tid + 256 * t;
        int r = idx >> 3, c8 = idx & 7;
        uint32_t off = (uint32_t)(r * LGH_ROWB + c8 * 16);
        cpa16(base + LGH_SA + off, &g_Xqh[m0 + r][kt * 64 + c8 * 8]);
    }
#pragma unroll
    for (int t = 0; t < 4; t++) {      // FIX: 1024 ops cover both 64x64 fp16 tiles
        int idx = tid + 256 * t;
        int tt = idx >> 9;
        int rr = (idx >> 3) & 63, c8 = idx & 7;
        uint32_t off = (uint32_t)(tt * 9216 + rr * LGH_ROWB + c8 * 16);
        int row = (jt0 + tt) * 64 + rr;
        cpa16(base + LGH_SB + off, &g_Vh[c][row][kt * 64 + c8 * 8]);
    }
}

__global__ __launch_bounds__(256) void k_logits_mma(float* __restrict__ out) {
    extern __shared__ char smem[];
    uint32_t sb = smem_u32(smem);
    int tid = threadIdx.x, lane = tid & 31, wid = tid >> 5;
    int wm = wid >> 1, wn = wid & 1;
    int c = blockIdx.y, m0 = blockIdx.x * 128;

    uint32_t aoff = (uint32_t)((wm * 32 + (lane & 15)) * LGH_ROWB + (lane >> 4) * 16);
    uint32_t boff = (uint32_t)((wn * 32 + ((lane & 16) >> 1) + (lane & 7)) * LGH_ROWB
                               + ((lane & 8) ? 16 : 0));

    float q2[2][2] = {}, qb[2][2] = {};

    for (int pj = 0; pj < 8; pj++) {
        int jt0 = 2 * pj, jt1 = jt0 + 1;
        float acc[2][2][4][4] = {};
        lg_stage(sb, 0, c, m0, jt0, 0, tid);
        CPA_COMMIT;
        for (int kt = 0; kt <= jt1; kt++) {
            if (kt < jt1) {
                lg_stage(sb, (kt + 1) & 1, c, m0, jt0, kt + 1, tid);
                CPA_COMMIT;
                CPA_WAIT1;
            } else {
                CPA_WAIT0;
            }
            __syncthreads();
            uint32_t s0 = sb + (uint32_t)((kt & 1) * LGH_STAGE);
            uint32_t aH = s0 + LGH_SA + aoff;
            uint32_t bH0 = s0 + LGH_SB + boff;
#pragma unroll
            for (int ks = 0; ks < 4; ks++) {
                uint32_t ah[2][4];
                ldsm4(ah[0], aH + ks * 32);
                ldsm4(ah[1], aH + 16 * LGH_ROWB + ks * 32);
#pragma unroll
                for (int t = 0; t < 2; t++) {
                    if (t == 0 && kt > jt0) continue;
                    uint32_t bh[8];
                    ldsm4(&bh[0], bH0 + t * 9216 + ks * 32);
                    ldsm4(&bh[4], bH0 + t * 9216 + 16 * LGH_ROWB + ks * 32);
#pragma unroll
                    for (int ms = 0; ms < 2; ms++)
#pragma unroll
                        for (int nt = 0; nt < 4; nt++)
                            mma16816h(acc[t][ms][nt], ah[ms], &bh[nt * 2]);
                }
            }
            __syncthreads();
        }
#pragma unroll
        for (int t = 0; t < 2; t++) {
            int jt = jt0 + t;
#pragma unroll
            for (int ms = 0; ms < 2; ms++)
#pragma unroll
                for (int nt = 0; nt < 4; nt++) {
                    int jc = jt * 64 + wn * 32 + nt * 8 + 2 * (lane & 3);
                    float s0 = g_s[c][jc], s1 = g_s[c][jc + 1];
                    float* d = acc[t][ms][nt];
                    q2[ms][0] += d[0] * d[0] + d[1] * d[1];
                    qb[ms][0] += d[0] * s0 + d[1] * s1;
                    q2[ms][1] += d[2] * d[2] + d[3] * d[3];
                    qb[ms][1] += d[2] * s0 + d[3] * s1;
                }
        }
    }

    __syncthreads();
    float* rq = (float*)smem;
    float* rb = (float*)(smem + 4096);
    int slot = wn * 4 + (lane & 3);
    int g = lane >> 2;
#pragma unroll
    for (int ms = 0; ms < 2; ms++)
#pragma unroll
        for (int go = 0; go < 2; go++) {
            int row = wm * 32 + ms * 16 + go * 8 + g;
            rq[row * 8 + slot] = q2[ms][go];
            rb[row * 8 + slot] = qb[ms][go];
        }
    __syncthreads();
    if (tid < 128) {
        float q2r = 0.f, qbr = 0.f;
#pragma unroll
        for (int t = 0; t < 8; t++) { q2r += rq[tid * 8 + t]; qbr += rb[tid * 8 + t]; }
        int row = m0 + tid;
        float dq = g_nx[row] - 2.f * g_xm[row][c] + g_mmc[c];
        float qm = q2r - 2.f * qbr + g_ssc[c];
        out[(size_t)row * CLS + c] = -0.9f * qm - 0.1f * dq;
    }
}

// ---------------- launch ----------------
extern "C" void kernel_launch(void* const* d_in, const int* in_sizes, int n_in,
                              void* d_out, int out_size) {
    const float* X     = (const float*)d_in[0];
    const int*   y     = (const int*)d_in[1];
    const float* Xq    = (const float*)d_in[2];
    const float* m     = (const float*)d_in[3];
    const float* kappa = (const float*)d_in[4];
    const float* nu    = (const float*)d_in[5];
    const float* td    = (const float*)d_in[6];
    const float* tl    = (const float*)d_in[7];
    float* out = (float*)d_out;

    cudaFuncSetAttribute(k_logits_mma, cudaFuncAttributeMaxDynamicSharedMemorySize, LGH_SMEM);

    k_stats1<<<dim3(8, 8), 128>>>(X, y);
    k_sort_params<<<1, 32>>>(y, kappa, nu);
    k_mu<<<dim3(4, CLS), 256>>>(m);
    k_cvt_xq<<<16384, 256>>>(Xq);
    k_buildL<<<D, 256>>>(td, tl);
    k_base<<<dim3(NT, NT), 256>>>(m);
    k_nxm<<<MQ / 8, 256>>>(Xq);

    k_sigma_mma<<<dim3(8, 16, CLS), 256>>>(X);
    k_chol_diag0<<<CLS, 256>>>();
    for (int kb = 0; kb < NT - 1; kb++) {
        int T = NT - 1 - kb;
        k_pgemm<<<dim3(T, CLS), 128>>>(kb);
        k_trail_mma<<<dim3(T * (T + 1) / 2, CLS), 128>>>(kb);
    }
    for (int s = 0; s < 4; s++) {
        int h = 64 << s;
        int tpr = h >> 6;
        int tiles = (D / (2 * h)) * tpr * tpr;
        k_tri1<<<dim3(tiles, CLS), 128>>>(h);
        k_tri2<<<dim3(tiles, CLS), 128>>>(h);
    }
    k_svec<<<dim3(D / 8, CLS), 256>>>();
    k_scalars<<<CLS, 256>>>();
    k_logits_mma<<<dim3(MQ / 128, CLS), 256, LGH_SMEM>>>(out);
}